// round 4
// baseline (speedup 1.0000x reference)
#include <cuda_runtime.h>
#include <math.h>

// Scratch (no cudaMalloc allowed): per-block partials + completion counter.
#define MAX_BLOCKS 16384
__device__ float g_partial[MAX_BLOCKS];
__device__ unsigned long long g_done_ctr;   // never reset: monotonic trick

template<bool IS_D512>
__global__ __launch_bounds__(256, 4) void assignment_loss_kernel(
    const float* __restrict__ emb,
    const void*  __restrict__ labels_raw,
    const float* __restrict__ protos,
    float* __restrict__ out,
    int B, int D, int C)
{
    const int wib  = threadIdx.x >> 5;          // warp in block (0..7)
    const int lane = threadIdx.x & 31;
    const int warp = blockIdx.x * 8 + wib;      // global sample id

    // ---- In-block label dtype detection (warp 0), broadcast via smem ----
    __shared__ int s_is64;
    if (threadIdx.x < 32) {
        int n = (B < 32) ? B : 32;
        bool ok = true;
        if (lane < n) {
            long long v = ((const long long*)labels_raw)[lane];
            ok = (v >= 0) && (v < (long long)C);
        }
        unsigned mask = __ballot_sync(0xFFFFFFFFu, ok);
        if (lane == 0) s_is64 = (mask == 0xFFFFFFFFu) ? 1 : 0;
    }
    __syncthreads();
    const int is64 = s_is64;

    // ---- Per-sample cosine (warp-per-sample) ----
    float dep = 0.f, dee = 0.f, dpp = 0.f;

    if (warp < B) {
        long long lab;
        if (is64) lab = ((const long long*)labels_raw)[warp];
        else      lab = (long long)((const int*)labels_raw)[warp];
        if (lab < 0) lab = 0;
        if (lab >= (long long)C) lab = C - 1;

        if (IS_D512) {
            const float4* e = reinterpret_cast<const float4*>(emb + (size_t)warp * 512);
            const float4* p = reinterpret_cast<const float4*>(protos + (size_t)lab * 512);

            // Batch ALL loads first: 8 outstanding LDG.128 per thread (MLP=8).
            float4 ev[4], pv[4];
            #pragma unroll
            for (int k = 0; k < 4; k++) ev[k] = e[lane + 32 * k];
            #pragma unroll
            for (int k = 0; k < 4; k++) pv[k] = p[lane + 32 * k];

            #pragma unroll
            for (int k = 0; k < 4; k++) {
                dep = fmaf(ev[k].x, pv[k].x, fmaf(ev[k].y, pv[k].y,
                      fmaf(ev[k].z, pv[k].z, fmaf(ev[k].w, pv[k].w, dep))));
                dee = fmaf(ev[k].x, ev[k].x, fmaf(ev[k].y, ev[k].y,
                      fmaf(ev[k].z, ev[k].z, fmaf(ev[k].w, ev[k].w, dee))));
                dpp = fmaf(pv[k].x, pv[k].x, fmaf(pv[k].y, pv[k].y,
                      fmaf(pv[k].z, pv[k].z, fmaf(pv[k].w, pv[k].w, dpp))));
            }
        } else {
            const float* e = emb + (size_t)warp * D;
            const float* p = protos + (size_t)lab * D;
            for (int i = lane; i < D; i += 32) {
                float evs = e[i], pvs = p[i];
                dep = fmaf(evs, pvs, dep);
                dee = fmaf(evs, evs, dee);
                dpp = fmaf(pvs, pvs, dpp);
            }
        }
    }

    #pragma unroll
    for (int off = 16; off > 0; off >>= 1) {
        dep += __shfl_xor_sync(0xFFFFFFFFu, dep, off);
        dee += __shfl_xor_sync(0xFFFFFFFFu, dee, off);
        dpp += __shfl_xor_sync(0xFFFFFFFFu, dpp, off);
    }

    __shared__ float s_cos[8];
    if (lane == 0) {
        float cosv = 0.f;
        if (warp < B) {
            float en = fmaxf(sqrtf(dee), 1e-8f);
            float pn = fmaxf(sqrtf(dpp), 1e-8f);
            cosv = dep / (en * pn);
        }
        s_cos[wib] = cosv;
    }
    __syncthreads();

    // ---- Block partial -> global slot, then last-block final reduce ----
    __shared__ bool s_last;
    if (threadIdx.x == 0) {
        float acc = 0.f;
        #pragma unroll
        for (int w = 0; w < 8; w++) acc += s_cos[w];
        g_partial[blockIdx.x] = acc;
        __threadfence();                              // partial visible GPU-wide
        unsigned long long old = atomicAdd(&g_done_ctr, 1ULL);
        s_last = ((old % (unsigned long long)gridDim.x) ==
                  (unsigned long long)(gridDim.x - 1));
    }
    __syncthreads();

    if (s_last) {
        double acc = 0.0;
        for (int i = threadIdx.x; i < gridDim.x; i += 256) {
            acc += (double)*((volatile float*)&g_partial[i]);
        }
        #pragma unroll
        for (int off = 16; off > 0; off >>= 1)
            acc += __shfl_xor_sync(0xFFFFFFFFu, acc, off);

        __shared__ double s_red[8];
        if (lane == 0) s_red[wib] = acc;
        __syncthreads();
        if (threadIdx.x == 0) {
            double total = 0.0;
            #pragma unroll
            for (int w = 0; w < 8; w++) total += s_red[w];
            out[0] = 1.0f - (float)(total / (double)B);
        }
    }
}

extern "C" void kernel_launch(void* const* d_in, const int* in_sizes, int n_in,
                              void* d_out, int out_size)
{
    // metadata order: embeddings [B*D] f32, labels [B], prototypes [C*D] f32
    const float* emb    = (const float*)d_in[0];
    const void*  labels = d_in[1];
    const float* protos = (const float*)d_in[2];
    float*       out    = (float*)d_out;

    const int B = in_sizes[1];
    const int D = in_sizes[0] / B;
    const int C = in_sizes[2] / D;

    int blocks = (B + 7) / 8;                  // 8 warps (samples) per block
    if (blocks > MAX_BLOCKS) blocks = MAX_BLOCKS;

    if (D == 512) {
        assignment_loss_kernel<true><<<blocks, 256>>>(emb, labels, protos, out, B, D, C);
    } else {
        assignment_loss_kernel<false><<<blocks, 256>>>(emb, labels, protos, out, B, D, C);
    }
}

// round 6
// speedup vs baseline: 1.0539x; 1.0539x over previous
#include <cuda_runtime.h>
#include <math.h>

// Scratch (no cudaMalloc allowed anywhere).
#define MAX_BLOCKS 4096
__device__ float g_partial[MAX_BLOCKS];
__device__ int   g_is64;

// --- 1. Label dtype detection: one warp, parallel ballot (~0.5us) ---------
__global__ void detect_kernel(const void* labels_raw, int B, int C) {
    const int lane = threadIdx.x;
    const int n = (B < 32) ? B : 32;
    bool ok = true;
    if (lane < n) {
        long long v = ((const long long*)labels_raw)[lane];
        ok = (v >= 0) && (v < (long long)C);
    }
    unsigned m = __ballot_sync(0xFFFFFFFFu, ok);
    if (lane == 0) g_is64 = (m == 0xFFFFFFFFu) ? 1 : 0;
}

// --- 2. Main: persistent warp-per-sample, 8 samples/warp ------------------
template<bool IS_D512>
__global__ __launch_bounds__(256) void cos_main(
    const float* __restrict__ emb,
    const void*  __restrict__ labels_raw,
    const float* __restrict__ protos,
    int B, int D, int C)
{
    const int wib   = threadIdx.x >> 5;
    const int lane  = threadIdx.x & 31;
    const int gwarp = blockIdx.x * 8 + wib;
    const int tw    = gridDim.x * 8;        // total warps
    const int is64  = g_is64;

    // Prefetch this warp's labels for up to 8 iterations: lane l holds iter l.
    long long lab_pre = 0;
    if (lane < 8) {
        long long s = (long long)gwarp + (long long)lane * tw;
        if (s < B) {
            if (is64) lab_pre = ((const long long*)labels_raw)[s];
            else      lab_pre = (long long)((const int*)labels_raw)[s];
            if (lab_pre < 0) lab_pre = 0;
            if (lab_pre >= (long long)C) lab_pre = C - 1;
        }
    }

    float cos_acc = 0.f;
    int iter = 0;
    for (int s = gwarp; s < B; s += tw, iter++) {
        long long lab;
        if (iter < 8) {
            lab = __shfl_sync(0xFFFFFFFFu, lab_pre, iter);
        } else {                              // generality fallback (unused at B=64K)
            if (is64) lab = ((const long long*)labels_raw)[s];
            else      lab = (long long)((const int*)labels_raw)[s];
            if (lab < 0) lab = 0;
            if (lab >= (long long)C) lab = C - 1;
        }

        float dep = 0.f, dee = 0.f, dpp = 0.f;

        if (IS_D512) {
            const float4* e = reinterpret_cast<const float4*>(emb + (size_t)s * 512);
            const float4* p = reinterpret_cast<const float4*>(protos + (size_t)lab * 512);
            float4 ev[4], pv[4];
            #pragma unroll
            for (int k = 0; k < 4; k++) ev[k] = e[lane + 32 * k];
            #pragma unroll
            for (int k = 0; k < 4; k++) pv[k] = p[lane + 32 * k];
            #pragma unroll
            for (int k = 0; k < 4; k++) {
                dep = fmaf(ev[k].x, pv[k].x, fmaf(ev[k].y, pv[k].y,
                      fmaf(ev[k].z, pv[k].z, fmaf(ev[k].w, pv[k].w, dep))));
                dee = fmaf(ev[k].x, ev[k].x, fmaf(ev[k].y, ev[k].y,
                      fmaf(ev[k].z, ev[k].z, fmaf(ev[k].w, ev[k].w, dee))));
                dpp = fmaf(pv[k].x, pv[k].x, fmaf(pv[k].y, pv[k].y,
                      fmaf(pv[k].z, pv[k].z, fmaf(pv[k].w, pv[k].w, dpp))));
            }
        } else {
            const float* e = emb + (size_t)s * D;
            const float* p = protos + (size_t)lab * D;
            for (int i = lane; i < D; i += 32) {
                float evs = e[i], pvs = p[i];
                dep = fmaf(evs, pvs, dep);
                dee = fmaf(evs, evs, dee);
                dpp = fmaf(pvs, pvs, dpp);
            }
        }

        #pragma unroll
        for (int off = 16; off > 0; off >>= 1) {
            dep += __shfl_xor_sync(0xFFFFFFFFu, dep, off);
            dee += __shfl_xor_sync(0xFFFFFFFFu, dee, off);
            dpp += __shfl_xor_sync(0xFFFFFFFFu, dpp, off);
        }

        if (lane == 0) {
            float en = fmaxf(sqrtf(dee), 1e-8f);
            float pn = fmaxf(sqrtf(dpp), 1e-8f);
            cos_acc += dep / (en * pn);
        }
    }

    // Per-block partial -> dedicated slot (no atomics, no reset needed).
    __shared__ float s_c[8];
    if (lane == 0) s_c[wib] = cos_acc;
    __syncthreads();
    if (threadIdx.x == 0) {
        float a = 0.f;
        #pragma unroll
        for (int w = 0; w < 8; w++) a += s_c[w];
        g_partial[blockIdx.x] = a;
    }
}

// --- 3. Finalize: reduce per-block partials, write scalar -----------------
__global__ __launch_bounds__(256) void finalize_kernel(float* out, int B, int nblocks) {
    const int lane = threadIdx.x & 31;
    const int wib  = threadIdx.x >> 5;
    double acc = 0.0;
    for (int i = threadIdx.x; i < nblocks; i += 256)
        acc += (double)g_partial[i];
    #pragma unroll
    for (int off = 16; off > 0; off >>= 1)
        acc += __shfl_xor_sync(0xFFFFFFFFu, acc, off);

    __shared__ double s_r[8];
    if (lane == 0) s_r[wib] = acc;
    __syncthreads();
    if (threadIdx.x == 0) {
        double total = 0.0;
        #pragma unroll
        for (int w = 0; w < 8; w++) total += s_r[w];
        out[0] = 1.0f - (float)(total / (double)B);
    }
}

extern "C" void kernel_launch(void* const* d_in, const int* in_sizes, int n_in,
                              void* d_out, int out_size)
{
    // metadata order: embeddings [B*D] f32, labels [B], prototypes [C*D] f32
    const float* emb    = (const float*)d_in[0];
    const void*  labels = d_in[1];
    const float* protos = (const float*)d_in[2];
    float*       out    = (float*)d_out;

    const int B = in_sizes[1];
    const int D = in_sizes[0] / B;
    const int C = in_sizes[2] / D;

    // ~8 samples per warp: blocks = ceil(B / (8 warps * 8 iters))
    int blocks = (B + 63) / 64;
    if (blocks < 1) blocks = 1;
    if (blocks > MAX_BLOCKS) blocks = MAX_BLOCKS;

    detect_kernel<<<1, 32>>>(labels, B, C);
    if (D == 512) {
        cos_main<true><<<blocks, 256>>>(emb, labels, protos, B, D, C);
    } else {
        cos_main<false><<<blocks, 256>>>(emb, labels, protos, B, D, C);
    }
    finalize_kernel<<<1, 256>>>(out, B, blocks);
}

// round 7
// speedup vs baseline: 1.1471x; 1.0884x over previous
#include <cuda_runtime.h>
#include <math.h>

// Scratch (no cudaMalloc anywhere): per-block partial slots, no reset needed.
#define MAX_BLOCKS 16384
__device__ float g_partial[MAX_BLOCKS];

// --- Main: R2's exact body (warp-per-sample, one-shot, interleaved loads),
//     with inline per-warp label-dtype detection and slot-write epilogue. ---
__global__ __launch_bounds__(256) void cos_main(
    const float* __restrict__ emb,
    const void*  __restrict__ labels_raw,
    const float* __restrict__ protos,
    int B, int D, int C)
{
    const int wib  = threadIdx.x >> 5;
    const int lane = threadIdx.x & 31;
    const int warp = blockIdx.x * 8 + wib;

    // Per-warp dtype detection: read labels[0..3] as int64 (32B, L2-hot
    // broadcast). If the buffer is int32, high halves hold random labels ->
    // values >= C with overwhelming probability (P(miss) ~ 1e-16).
    const long long* l64 = (const long long*)labels_raw;
    bool is64;
    {
        int nq = B >= 8 ? 4 : (B >= 2 ? B / 2 : 0);
        bool ok = (nq > 0);
        for (int i = 0; i < nq; i++) {
            unsigned long long v = (unsigned long long)l64[i];
            ok &= (v < (unsigned long long)C);
        }
        is64 = ok;
    }

    float dep = 0.f, dee = 0.f, dpp = 0.f;

    if (warp < B) {
        long long lab;
        if (is64) lab = l64[warp];
        else      lab = (long long)((const int*)labels_raw)[warp];
        if (lab < 0) lab = 0;
        if (lab >= (long long)C) lab = C - 1;

        if (D == 512) {
            const float4* e = reinterpret_cast<const float4*>(emb + (size_t)warp * 512);
            const float4* p = reinterpret_cast<const float4*>(protos + (size_t)lab * 512);
            #pragma unroll
            for (int k = 0; k < 4; k++) {
                float4 ev = e[lane + 32 * k];
                float4 pv = p[lane + 32 * k];
                dep = fmaf(ev.x, pv.x, fmaf(ev.y, pv.y, fmaf(ev.z, pv.z, fmaf(ev.w, pv.w, dep))));
                dee = fmaf(ev.x, ev.x, fmaf(ev.y, ev.y, fmaf(ev.z, ev.z, fmaf(ev.w, ev.w, dee))));
                dpp = fmaf(pv.x, pv.x, fmaf(pv.y, pv.y, fmaf(pv.z, pv.z, fmaf(pv.w, pv.w, dpp))));
            }
        } else {
            const float* e = emb + (size_t)warp * D;
            const float* p = protos + (size_t)lab * D;
            for (int i = lane; i < D; i += 32) {
                float evs = e[i], pvs = p[i];
                dep = fmaf(evs, pvs, dep);
                dee = fmaf(evs, evs, dee);
                dpp = fmaf(pvs, pvs, dpp);
            }
        }
    }

    #pragma unroll
    for (int off = 16; off > 0; off >>= 1) {
        dep += __shfl_xor_sync(0xFFFFFFFFu, dep, off);
        dee += __shfl_xor_sync(0xFFFFFFFFu, dee, off);
        dpp += __shfl_xor_sync(0xFFFFFFFFu, dpp, off);
    }

    __shared__ float s_cos[8];
    if (lane == 0) {
        float cosv = 0.f;
        if (warp < B) {
            float en = fmaxf(sqrtf(dee), 1e-8f);
            float pn = fmaxf(sqrtf(dpp), 1e-8f);
            cosv = dep / (en * pn);
        }
        s_cos[wib] = cosv;
    }
    __syncthreads();

    if (threadIdx.x == 0) {
        float acc = 0.f;
        #pragma unroll
        for (int w = 0; w < 8; w++) acc += s_cos[w];
        g_partial[blockIdx.x] = acc;   // dedicated slot: no reset, no atomic
    }
}

// --- Finalize: reduce per-block partials in double, write scalar. ---------
__global__ __launch_bounds__(256) void finalize_kernel(float* out, int B, int nblocks) {
    const int lane = threadIdx.x & 31;
    const int wib  = threadIdx.x >> 5;
    double acc = 0.0;
    for (int i = threadIdx.x; i < nblocks; i += 256)
        acc += (double)g_partial[i];
    #pragma unroll
    for (int off = 16; off > 0; off >>= 1)
        acc += __shfl_xor_sync(0xFFFFFFFFu, acc, off);

    __shared__ double s_r[8];
    if (lane == 0) s_r[wib] = acc;
    __syncthreads();
    if (threadIdx.x == 0) {
        double total = 0.0;
        #pragma unroll
        for (int w = 0; w < 8; w++) total += s_r[w];
        out[0] = 1.0f - (float)(total / (double)B);
    }
}

extern "C" void kernel_launch(void* const* d_in, const int* in_sizes, int n_in,
                              void* d_out, int out_size)
{
    // metadata order: embeddings [B*D] f32, labels [B], prototypes [C*D] f32
    const float* emb    = (const float*)d_in[0];
    const void*  labels = d_in[1];
    const float* protos = (const float*)d_in[2];
    float*       out    = (float*)d_out;

    const int B = in_sizes[1];
    const int D = in_sizes[0] / B;
    const int C = in_sizes[2] / D;

    int blocks = (B + 7) / 8;                  // 8 warps (samples) per block
    if (blocks > MAX_BLOCKS) blocks = MAX_BLOCKS;  // B<=128K with this config

    cos_main<<<blocks, 256>>>(emb, labels, protos, B, D, C);
    finalize_kernel<<<1, 256>>>(out, B, blocks);
}

// round 9
// speedup vs baseline: 1.3034x; 1.1362x over previous
#include <cuda_runtime.h>
#include <math.h>

// Single accumulator. Statically zero; finalize_kernel resets it after each
// read, so every graph replay starts from 0. No init kernel needed.
__device__ double g_cos_sum = 0.0;

// --- Main: warp-per-sample, one-shot, interleaved float4 loads (R2 body),
//     inline per-warp label-dtype detection, atomicAdd(double) epilogue. ---
__global__ __launch_bounds__(256) void cos_main(
    const float* __restrict__ emb,
    const void*  __restrict__ labels_raw,
    const float* __restrict__ protos,
    int B, int D, int C)
{
    const int wib  = threadIdx.x >> 5;
    const int lane = threadIdx.x & 31;
    const int warp = blockIdx.x * 8 + wib;

    // Per-warp dtype detection: read labels[0..3] as int64 (32B, L2-hot
    // broadcast). If the buffer is int32, the high halves hold random labels
    // -> some value >= C with overwhelming probability (P(miss) ~ 1e-16).
    const long long* l64 = (const long long*)labels_raw;
    bool is64;
    {
        int nq = B >= 8 ? 4 : (B >= 2 ? B / 2 : 0);
        bool ok = (nq > 0);
        for (int i = 0; i < nq; i++) {
            unsigned long long v = (unsigned long long)l64[i];
            ok &= (v < (unsigned long long)C);
        }
        is64 = ok;
    }

    float dep = 0.f, dee = 0.f, dpp = 0.f;

    if (warp < B) {
        long long lab;
        if (is64) lab = l64[warp];
        else      lab = (long long)((const int*)labels_raw)[warp];
        if (lab < 0) lab = 0;
        if (lab >= (long long)C) lab = C - 1;

        if (D == 512) {
            const float4* e = reinterpret_cast<const float4*>(emb + (size_t)warp * 512);
            const float4* p = reinterpret_cast<const float4*>(protos + (size_t)lab * 512);
            #pragma unroll
            for (int k = 0; k < 4; k++) {
                float4 ev = e[lane + 32 * k];
                float4 pv = p[lane + 32 * k];
                dep = fmaf(ev.x, pv.x, fmaf(ev.y, pv.y, fmaf(ev.z, pv.z, fmaf(ev.w, pv.w, dep))));
                dee = fmaf(ev.x, ev.x, fmaf(ev.y, ev.y, fmaf(ev.z, ev.z, fmaf(ev.w, ev.w, dee))));
                dpp = fmaf(pv.x, pv.x, fmaf(pv.y, pv.y, fmaf(pv.z, pv.z, fmaf(pv.w, pv.w, dpp))));
            }
        } else {
            const float* e = emb + (size_t)warp * D;
            const float* p = protos + (size_t)lab * D;
            for (int i = lane; i < D; i += 32) {
                float evs = e[i], pvs = p[i];
                dep = fmaf(evs, pvs, dep);
                dee = fmaf(evs, evs, dee);
                dpp = fmaf(pvs, pvs, dpp);
            }
        }
    }

    #pragma unroll
    for (int off = 16; off > 0; off >>= 1) {
        dep += __shfl_xor_sync(0xFFFFFFFFu, dep, off);
        dee += __shfl_xor_sync(0xFFFFFFFFu, dee, off);
        dpp += __shfl_xor_sync(0xFFFFFFFFu, dpp, off);
    }

    __shared__ float s_cos[8];
    if (lane == 0) {
        float cosv = 0.f;
        if (warp < B) {
            float en = fmaxf(sqrtf(dee), 1e-8f);
            float pn = fmaxf(sqrtf(dpp), 1e-8f);
            cosv = dep / (en * pn);
        }
        s_cos[wib] = cosv;
    }
    __syncthreads();

    if (threadIdx.x == 0) {
        float acc = 0.f;
        #pragma unroll
        for (int w = 0; w < 8; w++) acc += s_cos[w];
        atomicAdd(&g_cos_sum, (double)acc);
    }
}

// --- Finalize: read scalar, write output, reset accumulator for replay. ---
__global__ void finalize_kernel(float* out, int B) {
    out[0] = 1.0f - (float)(g_cos_sum / (double)B);
    g_cos_sum = 0.0;                 // ready for next graph replay
}

extern "C" void kernel_launch(void* const* d_in, const int* in_sizes, int n_in,
                              void* d_out, int out_size)
{
    // metadata order: embeddings [B*D] f32, labels [B], prototypes [C*D] f32
    const float* emb    = (const float*)d_in[0];
    const void*  labels = d_in[1];
    const float* protos = (const float*)d_in[2];
    float*       out    = (float*)d_out;

    const int B = in_sizes[1];
    const int D = in_sizes[0] / B;
    const int C = in_sizes[2] / D;

    int blocks = (B + 7) / 8;                  // 8 warps (samples) per block

    cos_main<<<blocks, 256>>>(emb, labels, protos, B, D, C);
    finalize_kernel<<<1, 1>>>(out, B);
}

// round 11
// speedup vs baseline: 1.3668x; 1.0486x over previous
#include <cuda_runtime.h>
#include <math.h>

// Single packed accumulator: bits [44:57) = block completion counter,
// bits [0:44) = biased fixed-point (2^20) sum of per-block cosine partials.
// Statically zero; the last block resets it each launch -> graph-replay safe.
__device__ unsigned long long g_acc = 0ULL;

#define FIX_SHIFT 20
#define FIX_ONE   (1048576.0f)            // 2^20
#define BIAS      (1LL << 24)             // per-block bias, makes adds positive
#define CNT_SHIFT 44
#define SUM_MASK  ((1ULL << CNT_SHIFT) - 1ULL)

// --- Single fused kernel: warp-per-sample cosine + packed-atomic finish. ---
__global__ __launch_bounds__(256) void cos_main(
    const float* __restrict__ emb,
    const void*  __restrict__ labels_raw,
    const float* __restrict__ protos,
    float* __restrict__ out,
    int B, int D, int C)
{
    const int wib  = threadIdx.x >> 5;
    const int lane = threadIdx.x & 31;
    const int warp = blockIdx.x * 8 + wib;

    // Per-warp label dtype detection: read labels[0..3] as int64 (32B, L2-hot
    // broadcast). int32 buffer -> high halves hold random labels -> >= C with
    // overwhelming probability (P(miss) ~ 1e-16). Uniform in warp, no sync.
    const long long* l64 = (const long long*)labels_raw;
    bool is64;
    {
        int nq = B >= 8 ? 4 : (B >= 2 ? B / 2 : 0);
        bool ok = (nq > 0);
        for (int i = 0; i < nq; i++) {
            unsigned long long v = (unsigned long long)l64[i];
            ok &= (v < (unsigned long long)C);
        }
        is64 = ok;
    }

    float dep = 0.f, dee = 0.f, dpp = 0.f;

    if (warp < B) {
        long long lab;
        if (is64) lab = l64[warp];
        else      lab = (long long)((const int*)labels_raw)[warp];
        if (lab < 0) lab = 0;
        if (lab >= (long long)C) lab = C - 1;

        if (D == 512) {
            const float4* e = reinterpret_cast<const float4*>(emb + (size_t)warp * 512);
            const float4* p = reinterpret_cast<const float4*>(protos + (size_t)lab * 512);
            #pragma unroll
            for (int k = 0; k < 4; k++) {
                float4 ev = e[lane + 32 * k];
                float4 pv = p[lane + 32 * k];
                dep = fmaf(ev.x, pv.x, fmaf(ev.y, pv.y, fmaf(ev.z, pv.z, fmaf(ev.w, pv.w, dep))));
                dee = fmaf(ev.x, ev.x, fmaf(ev.y, ev.y, fmaf(ev.z, ev.z, fmaf(ev.w, ev.w, dee))));
                dpp = fmaf(pv.x, pv.x, fmaf(pv.y, pv.y, fmaf(pv.z, pv.z, fmaf(pv.w, pv.w, dpp))));
            }
        } else {
            const float* e = emb + (size_t)warp * D;
            const float* p = protos + (size_t)lab * D;
            for (int i = lane; i < D; i += 32) {
                float evs = e[i], pvs = p[i];
                dep = fmaf(evs, pvs, dep);
                dee = fmaf(evs, evs, dee);
                dpp = fmaf(pvs, pvs, dpp);
            }
        }
    }

    #pragma unroll
    for (int off = 16; off > 0; off >>= 1) {
        dep += __shfl_xor_sync(0xFFFFFFFFu, dep, off);
        dee += __shfl_xor_sync(0xFFFFFFFFu, dee, off);
        dpp += __shfl_xor_sync(0xFFFFFFFFu, dpp, off);
    }

    __shared__ float s_cos[8];
    if (lane == 0) {
        float cosv = 0.f;
        if (warp < B) {
            float en = fmaxf(sqrtf(dee), 1e-8f);
            float pn = fmaxf(sqrtf(dpp), 1e-8f);
            cosv = dep / (en * pn);
        }
        s_cos[wib] = cosv;
    }
    __syncthreads();

    if (threadIdx.x == 0) {
        float acc = 0.f;
        #pragma unroll
        for (int w = 0; w < 8; w++) acc += s_cos[w];

        // Pack: counter +1 in high bits, biased fixed-point partial in low.
        // |acc| <= 8  ->  fixed in [BIAS - 2^23, BIAS + 2^23], always > 0.
        long long fixed = __float2ll_rn(acc * FIX_ONE) + BIAS;
        unsigned long long add = (1ULL << CNT_SHIFT) | (unsigned long long)fixed;
        unsigned long long old = atomicAdd(&g_acc, add);

        if ((unsigned)(old >> CNT_SHIFT) == (unsigned)(gridDim.x - 1)) {
            // Last block: all contributions (incl. ours) are in old + add.
            unsigned long long total = old + add;
            long long fixsum = (long long)(total & SUM_MASK)
                             - (long long)gridDim.x * BIAS;
            double sum = (double)fixsum / (double)FIX_ONE;
            out[0] = 1.0f - (float)(sum / (double)B);
            atomicExch(&g_acc, 0ULL);          // reset for next graph replay
        }
    }
}

extern "C" void kernel_launch(void* const* d_in, const int* in_sizes, int n_in,
                              void* d_out, int out_size)
{
    // metadata order: embeddings [B*D] f32, labels [B], prototypes [C*D] f32
    const float* emb    = (const float*)d_in[0];
    const void*  labels = d_in[1];
    const float* protos = (const float*)d_in[2];
    float*       out    = (float*)d_out;

    const int B = in_sizes[1];
    const int D = in_sizes[0] / B;
    const int C = in_sizes[2] / D;

    int blocks = (B + 7) / 8;                  // 8 warps (samples) per block

    cos_main<<<blocks, 256>>>(emb, labels, protos, out, B, D, C);
}